// round 15
// baseline (speedup 1.0000x reference)
#include <cuda_runtime.h>
#include <cuda_bf16.h>

#define O_    4
#define N_    3072
#define KNN   10
#define TOLC  0.01f
#define FMAXV 3.402823466e+38f
#define BTHR  128            // threads per knn block (1 query/thread)
#define CAP   64             // per-thread insert buffer (mean ~15 outward, ~7 sigma)
#define NCH   96             // chunks of 32 candidates
#define NS    4096           // bitonic pad
#define FULLM 0xFFFFFFFFu

// ---------------- device scratch (no allocations allowed) ----------------
__device__ float4 g_pip4[O_ * N_];     // (x, y, z, |p|^2), original order
__device__ float4 g_nrm4[O_ * N_];     // raw normal, original order
__device__ float4 g_spip[O_][N_];      // x-sorted positions
__device__ float4 g_snrm[O_][N_];      // x-sorted normals
__device__ int    g_sid [O_][N_];      // sorted rank -> original index
__device__ float  g_scr[O_][3][N_];    // signed nearest distance (original index)

__device__ __forceinline__ unsigned f2ord(float f) {
    unsigned b = __float_as_uint(f);
    return b ^ ((unsigned)(((int)b) >> 31) | 0x80000000u);
}

// ---------------- kernel 1: prep + transform fused ----------------
__global__ void transform_kernel(const float* __restrict__ points,
                                 const float* __restrict__ T_obj,
                                 const float* __restrict__ T_plane) {
    int i = blockIdx.x * blockDim.x + threadIdx.x;
    if (i >= O_ * N_) return;
    int o = i / N_;

    float Rp[9], tp[3];
    #pragma unroll
    for (int r = 0; r < 3; r++) {
        #pragma unroll
        for (int c = 0; c < 3; c++) Rp[r * 3 + c] = __ldg(&T_plane[r * 4 + c]);
        tp[r] = __ldg(&T_plane[r * 4 + 3]);
    }
    const float* To = T_obj + o * 16;
    // inv(T_plane) rigid: [Rp^T | -Rp^T tp]
    float R[3][3], tr[3];
    #pragma unroll
    for (int r = 0; r < 3; r++) {
        R[r][0] = Rp[0 + r] * To[0] + Rp[3 + r] * To[4] + Rp[6 + r] * To[8];
        R[r][1] = Rp[0 + r] * To[1] + Rp[3 + r] * To[5] + Rp[6 + r] * To[9];
        R[r][2] = Rp[0 + r] * To[2] + Rp[3 + r] * To[6] + Rp[6 + r] * To[10];
        tr[r]   = Rp[0 + r] * (To[3] - tp[0]) + Rp[3 + r] * (To[7] - tp[1])
                + Rp[6 + r] * (To[11] - tp[2]);
    }

    const float* p = points + (size_t)i * 6;
    float x = p[0], y = p[1], z = p[2];
    float px = fmaf(R[0][0], x, fmaf(R[0][1], y, fmaf(R[0][2], z, tr[0])));
    float py = fmaf(R[1][0], x, fmaf(R[1][1], y, fmaf(R[1][2], z, tr[1])));
    float pz = fmaf(R[2][0], x, fmaf(R[2][1], y, fmaf(R[2][2], z, tr[2])));
    float rr = px * px + py * py + pz * pz;
    g_pip4[i] = make_float4(px, py, pz, rr);
    g_nrm4[i] = make_float4(p[3], p[4], p[5], 0.f);
}

// ---------------- kernel 1b: exact x-sort per object (bitonic, R10-validated) ----------------
__global__ void __launch_bounds__(1024) sortx_kernel() {
    __shared__ unsigned long long sk[NS];
    int o = blockIdx.x;
    for (int i = threadIdx.x; i < NS; i += 1024) {
        unsigned long long key = 0xFFFFFFFFFFFFFFFFull;
        if (i < N_)
            key = ((unsigned long long)f2ord(g_pip4[o * N_ + i].x) << 12) | (unsigned)i;
        sk[i] = key;
    }
    __syncthreads();
    for (int k = 2; k <= NS; k <<= 1) {
        for (int j = k >> 1; j > 0; j >>= 1) {
            for (int i = threadIdx.x; i < NS; i += 1024) {
                int ixj = i ^ j;
                if (ixj > i) {
                    unsigned long long a = sk[i], b = sk[ixj];
                    bool up = ((i & k) == 0);
                    if ((a > b) == up) { sk[i] = b; sk[ixj] = a; }
                }
            }
            __syncthreads();
        }
    }
    for (int r = threadIdx.x; r < N_; r += 1024) {
        int idx = (int)(sk[r] & 0xFFFu);
        g_spip[o][r] = g_pip4[o * N_ + idx];
        g_snrm[o][r] = g_nrm4[o * N_ + idx];
        g_sid [o][r] = idx;
    }
}

// ---------------- kernel 2: outward chunk expansion + bitmask collect/replay ----------------
// smem: [0,48K) sorted candidates ; buf u16 [CAP][BTHR] (16K) ; cmin/cmax [NCH]
__global__ void __launch_bounds__(BTHR) knn_kernel() {
    extern __shared__ float4 sh[];                       // N_ sorted candidates
    unsigned short* buf = (unsigned short*)(sh + N_);    // buf[slot*BTHR + tid]
    float* cmin = (float*)(buf + CAP * BTHR);            // [NCH]
    float* cmax = cmin + NCH;                            // [NCH]

    int pair = blockIdx.y;
    int b  = pair / 3;
    int oi = pair - b * 3;
    int o  = oi + (oi >= b ? 1 : 0);
    int tid = threadIdx.x;
    int qrank = blockIdx.x * BTHR + tid;                 // sorted query rank

    const float4* cand = &g_spip[o][0];
    for (int i = tid; i < N_; i += BTHR) sh[i] = cand[i];
    __syncthreads();
    if (tid < NCH) {
        cmin[tid] = sh[tid * 32].x;
        cmax[tid] = sh[tid * 32 + 31].x;
    }
    __syncthreads();

    float4 q = g_spip[b][qrank];
    int orig_n = g_sid[b][qrank];
    float m2x = -2.f * q.x, m2y = -2.f * q.y, m2z = -2.f * q.z;

    float a[KNN];
    #pragma unroll
    for (int s = 0; s < KNN; s++) a[s] = FMAXV;
    float thresh = FMAXV;
    int cnt = 0;

    // one chunk: bitmask collect (branchless) + recheck replay (R12-validated)
    #define SCAN_CHUNK(ch)                                                    \
        do { int _j0 = (ch) * 32;                                             \
             unsigned _mask = 0u;                                             \
             _Pragma("unroll")                                                \
             for (int _u = 0; _u < 32; _u++) {                                \
                 float4 _c = sh[_j0 + _u];                                    \
                 float _d = fmaf(_c.x, m2x,                                   \
                            fmaf(_c.y, m2y, fmaf(_c.z, m2z, _c.w)));          \
                 _mask |= (_d < thresh) ? (1u << _u) : 0u;                    \
             }                                                                \
             _Pragma("unroll 1")                                              \
             while (__any_sync(FULLM, _mask != 0u)) {                         \
                 if (_mask) {                                                 \
                     int _bit = __ffs(_mask) - 1;                             \
                     _mask &= _mask - 1u;                                     \
                     int _id = _j0 + _bit;                                    \
                     float4 _c = sh[_id];                                     \
                     float _d = fmaf(_c.x, m2x,                               \
                                fmaf(_c.y, m2y, fmaf(_c.z, m2z, _c.w)));      \
                     if (_d < thresh) {                                       \
                         int _slot = cnt < CAP - 1 ? cnt : CAP - 1;           \
                         buf[_slot * BTHR + tid] = (unsigned short)_id;       \
                         cnt++;                                               \
                         float _t = _d;                                       \
                         _Pragma("unroll")                                    \
                         for (int _s = 0; _s < KNN; _s++) {                   \
                             float _lo = fminf(a[_s], _t);                    \
                             _t = fmaxf(a[_s], _t);                           \
                             a[_s] = _lo;                                     \
                         }                                                    \
                         thresh = a[KNN - 1];                                 \
                     }                                                        \
                 }                                                            \
             } } while (0)

    // home chunk: binary search on cmin (lane 16's query, warp-uniform via shfl)
    int lo = 0, hi = NCH - 1;
    #pragma unroll
    for (int it = 0; it < 7; it++) {
        int mid = (lo + hi + 1) >> 1;
        if (cmin[mid] <= q.x) lo = mid; else hi = mid - 1;
    }
    int hc = __shfl_sync(FULLM, lo, 16);

    SCAN_CHUNK(hc);

    // expand outward with exact pruning: D >= gap_x^2 ; gaps monotone per direction
    {
        int up = hc + 1, dn = hc - 1;
        #pragma unroll 1
        while (up < NCH || dn >= 0) {
            if (up < NCH) {
                float gap = fmaxf(0.f, cmin[up] - q.x);
                bool need = gap * gap <= q.w + thresh;
                if (__any_sync(FULLM, need)) { SCAN_CHUNK(up); up++; }
                else up = NCH;
            }
            if (dn >= 0) {
                float gap = fmaxf(0.f, q.x - cmax[dn]);
                bool need = gap * gap <= q.w + thresh;
                if (__any_sync(FULLM, need)) { SCAN_CHUNK(dn); dn--; }
                else dn = -1;
            }
        }
    }
    // a[0..9] is the EXACT top-10: scanned candidates below the running threshold
    // were replayed (threshold only decreases); pruned chunks provably contain
    // no candidate with D <= q.w + a9_final.

    // ---- final id selection (sorted ranks) ----
    unsigned ids[KNN];
    int w = 0;
    if (cnt < CAP) {
        #pragma unroll 1
        for (int t = 0; t < cnt && w < KNN; t++) {
            unsigned id = buf[t * BTHR + tid];
            float4 c = sh[id];
            float d = fmaf(c.x, m2x, fmaf(c.y, m2y, fmaf(c.z, m2z, c.w)));
            if (d <= thresh) ids[w++] = id;
        }
    } else {
        // overflow fallback: exact full rescan (threshold a[] may have been fed
        // only scanned chunks, which is exact; rebuild ids from full array)
        #pragma unroll 1
        for (int j = 0; j < N_ && w < KNN; j++) {
            float4 c = sh[j];
            float d = fmaf(c.x, m2x, fmaf(c.y, m2y, fmaf(c.z, m2z, c.w)));
            if (d <= thresh) ids[w++] = (unsigned)j;
        }
    }
    while (w < KNN) ids[w++] = ids[0];   // safety (unreachable)

    // ---- exact d0 + inside votes ----
    float D = q.w + a[0];
    float d0 = sqrtf(fmaxf(D, 0.f));

    int votes = 0;
    const float4* nrm = &g_snrm[o][0];
    #pragma unroll
    for (int s = 0; s < KNN; s++) {
        unsigned id = ids[s];
        float4 c  = sh[id];
        float4 nm = __ldg(&nrm[id]);
        float dt = (c.x - q.x) * nm.x + (c.y - q.y) * nm.y + (c.z - q.z) * nm.z;
        votes += (dt > 0.f) ? 1 : 0;
    }
    float sd = (votes > 8) ? -d0 : d0;   // sum(insides) > 0.8*k -> >= 9
    g_scr[b][oi][orig_n] = sd;

    #undef SCAN_CHUNK
}

// ---------------- kernel 3: min over other objects + plane, write out ----------------
__global__ void finalize_kernel(float* __restrict__ out, int out_size) {
    int i = blockIdx.x * blockDim.x + threadIdx.x;
    if (i >= O_ * N_) return;
    int b = i / N_;
    int n = i % N_;
    float sd = g_pip4[i].z;                 // plane signed distance = pip.z
    sd = fminf(sd, g_scr[b][0][n]);
    sd = fminf(sd, g_scr[b][1][n]);
    sd = fminf(sd, g_scr[b][2][n]);
    out[i] = sd;
    if (out_size >= 2 * O_ * N_)
        out[O_ * N_ + i] = (sd < -TOLC) ? 1.0f : 0.0f;
}

// ---------------- launch ----------------
extern "C" void kernel_launch(void* const* d_in, const int* in_sizes, int n_in,
                              void* d_out, int out_size) {
    const float* points  = nullptr;
    const float* T_obj   = nullptr;
    const float* T_plane = nullptr;
    for (int i = 0; i < n_in; i++) {
        if (in_sizes[i] == O_ * N_ * 6) points  = (const float*)d_in[i];
        else if (in_sizes[i] == 64)     T_obj   = (const float*)d_in[i];
        else if (in_sizes[i] == 16)     T_plane = (const float*)d_in[i];
    }

    transform_kernel<<<(O_ * N_ + 255) / 256, 256>>>(points, T_obj, T_plane);
    sortx_kernel<<<O_, 1024>>>();

    int smem = N_ * (int)sizeof(float4) + CAP * BTHR * (int)sizeof(unsigned short)
             + 2 * NCH * (int)sizeof(float);
    (void)cudaFuncSetAttribute(knn_kernel,
                               cudaFuncAttributeMaxDynamicSharedMemorySize, smem);
    knn_kernel<<<dim3(N_ / BTHR, O_ * 3), BTHR, smem>>>();

    finalize_kernel<<<(O_ * N_ + 255) / 256, 256>>>((float*)d_out, out_size);
}

// round 16
// speedup vs baseline: 2.8770x; 2.8770x over previous
#include <cuda_runtime.h>
#include <cuda_bf16.h>

#define O_    4
#define N_    3072
#define NSPL  2
#define LSPL  (N_ / NSPL)    // 1536 candidates per split
#define KNN   10
#define TOLC  0.01f
#define FMAXV 3.402823466e+38f
#define BTHR  128            // threads per knn block (1 query/thread)
#define CAP   112            // per-thread insert buffer (mean ~54, ~8 sigma)
#define FULLM 0xFFFFFFFFu

// ---------------- device scratch (no allocations allowed) ----------------
__device__ float4 g_pip4[O_ * N_];                 // (x, y, z, |p|^2)
__device__ float4 g_nrm4[O_ * N_];                 // raw normal
__device__ unsigned long long g_part[O_ * 3][NSPL][KNN][N_];  // sorted partial keys

// ordered-float helpers
__device__ __forceinline__ unsigned f2ord(float f) {
    unsigned b = __float_as_uint(f);
    return b ^ ((unsigned)(((int)b) >> 31) | 0x80000000u);
}
__device__ __forceinline__ float ord2f(unsigned u) {
    int ib = (u & 0x80000000u) ? (int)(u ^ 0x80000000u) : ~(int)u;
    return __int_as_float(ib);
}

// ---------------- kernel 1: prep + transform fused ----------------
__global__ void transform_kernel(const float* __restrict__ points,
                                 const float* __restrict__ T_obj,
                                 const float* __restrict__ T_plane) {
    int i = blockIdx.x * blockDim.x + threadIdx.x;
    if (i >= O_ * N_) return;
    int o = i / N_;

    float Rp[9], tp[3];
    #pragma unroll
    for (int r = 0; r < 3; r++) {
        #pragma unroll
        for (int c = 0; c < 3; c++) Rp[r * 3 + c] = __ldg(&T_plane[r * 4 + c]);
        tp[r] = __ldg(&T_plane[r * 4 + 3]);
    }
    const float* To = T_obj + o * 16;
    // inv(T_plane) rigid: [Rp^T | -Rp^T tp]
    float R[3][3], tr[3];
    #pragma unroll
    for (int r = 0; r < 3; r++) {
        R[r][0] = Rp[0 + r] * To[0] + Rp[3 + r] * To[4] + Rp[6 + r] * To[8];
        R[r][1] = Rp[0 + r] * To[1] + Rp[3 + r] * To[5] + Rp[6 + r] * To[9];
        R[r][2] = Rp[0 + r] * To[2] + Rp[3 + r] * To[6] + Rp[6 + r] * To[10];
        tr[r]   = Rp[0 + r] * (To[3] - tp[0]) + Rp[3 + r] * (To[7] - tp[1])
                + Rp[6 + r] * (To[11] - tp[2]);
    }

    const float* p = points + (size_t)i * 6;
    float x = p[0], y = p[1], z = p[2];
    float px = fmaf(R[0][0], x, fmaf(R[0][1], y, fmaf(R[0][2], z, tr[0])));
    float py = fmaf(R[1][0], x, fmaf(R[1][1], y, fmaf(R[1][2], z, tr[1])));
    float pz = fmaf(R[2][0], x, fmaf(R[2][1], y, fmaf(R[2][2], z, tr[2])));
    float rr = px * px + py * py + pz * pz;
    g_pip4[i] = make_float4(px, py, pz, rr);
    g_nrm4[i] = make_float4(p[3], p[4], p[5], 0.f);
}

// ---------------- kernel 2: bitmask-scan partial top-10 over one split ----------------
// blockIdx = (query chunk, pair, split); smem: LSPL float4 (24K) + buf u16 (28K)
__global__ void __launch_bounds__(BTHR) knn_partial_kernel() {
    extern __shared__ float4 sh[];                      // LSPL candidates
    unsigned short* buf = (unsigned short*)(sh + LSPL); // buf[slot*BTHR + tid]
    int pair = blockIdx.y;
    int spl  = blockIdx.z;
    int b  = pair / 3;
    int oi = pair - b * 3;
    int o  = oi + (oi >= b ? 1 : 0);
    int tid = threadIdx.x;
    int n  = blockIdx.x * BTHR + tid;
    int jbase = spl * LSPL;

    const float4* cand = g_pip4 + o * N_ + jbase;
    for (int i = tid; i < LSPL; i += BTHR) sh[i] = cand[i];
    __syncthreads();

    float4 q = g_pip4[b * N_ + n];
    float m2x = -2.f * q.x, m2y = -2.f * q.y, m2z = -2.f * q.z;

    float a[KNN];
    #pragma unroll
    for (int s = 0; s < KNN; s++) a[s] = FMAXV;
    float thresh = FMAXV;
    int cnt = 0;

    // ---- R12-validated scan: 32-candidate chunks, bitmask collect + recheck replay ----
    #pragma unroll 1
    for (int j0 = 0; j0 < LSPL; j0 += 32) {
        unsigned mask = 0u;
        #pragma unroll
        for (int u = 0; u < 32; u++) {
            float4 c = sh[j0 + u];      // warp-uniform address -> broadcast
            float d = fmaf(c.x, m2x, fmaf(c.y, m2y, fmaf(c.z, m2z, c.w)));
            mask |= (d < thresh) ? (1u << u) : 0u;
        }
        #pragma unroll 1
        while (__any_sync(FULLM, mask != 0u)) {
            if (mask) {
                int bit = __ffs(mask) - 1;
                mask &= mask - 1u;
                int id = j0 + bit;
                float4 c = sh[id];
                float d = fmaf(c.x, m2x, fmaf(c.y, m2y, fmaf(c.z, m2z, c.w)));
                if (d < thresh) {
                    int slot = cnt < CAP - 1 ? cnt : CAP - 1;
                    buf[slot * BTHR + tid] = (unsigned short)id;
                    cnt++;
                    float t = d;
                    #pragma unroll
                    for (int s = 0; s < KNN; s++) {
                        float lo = fminf(a[s], t);
                        t = fmaxf(a[s], t);
                        a[s] = lo;
                    }
                    thresh = a[KNN - 1];
                }
            }
        }
    }
    // a[0..9] is the EXACT split top-10 (superset argument, R12-proven).

    // ---- id selection: first 10 buffered (ascending local id) with d <= a[9] ----
    unsigned ids[KNN];
    int w = 0;
    if (cnt < CAP) {
        #pragma unroll 1
        for (int t = 0; t < cnt && w < KNN; t++) {
            unsigned id = buf[t * BTHR + tid];
            float4 c = sh[id];
            float d = fmaf(c.x, m2x, fmaf(c.y, m2y, fmaf(c.z, m2z, c.w)));
            if (d <= thresh) ids[w++] = id;
        }
    } else {
        // overflow fallback (P ~ 1e-10/thread): exact rescan ascending
        #pragma unroll 1
        for (int j = 0; j < LSPL && w < KNN; j++) {
            float4 c = sh[j];
            float d = fmaf(c.x, m2x, fmaf(c.y, m2y, fmaf(c.z, m2z, c.w)));
            if (d <= thresh) ids[w++] = (unsigned)j;
        }
    }
    while (w < KNN) ids[w++] = ids[0];   // safety (unreachable: LSPL >= KNN)

    // ---- build sorted u64 keys (ord(d)<<32 | global id) — R4-validated ----
    unsigned long long k[KNN];
    #pragma unroll
    for (int s = 0; s < KNN; s++) k[s] = 0xFFFFFFFFFFFFFFFFull;
    #pragma unroll
    for (int t = 0; t < KNN; t++) {
        unsigned id = ids[t];
        float4 c = sh[id];
        float d = fmaf(c.x, m2x, fmaf(c.y, m2y, fmaf(c.z, m2z, c.w)));
        unsigned long long key =
            ((unsigned long long)f2ord(d) << 32) | (unsigned)(jbase + id);
        #pragma unroll
        for (int s = 0; s < KNN; s++) {
            unsigned long long lo = (k[s] < key) ? k[s] : key;
            key = (k[s] < key) ? key : k[s];
            k[s] = lo;
        }
    }
    #pragma unroll
    for (int s = 0; s < KNN; s++) g_part[pair][spl][s][n] = k[s];
}

// ---------------- kernel 3: merge partials + votes + plane min + output (R4-validated) ----------------
__global__ void merge_kernel(float* __restrict__ out, int out_size) {
    int i = blockIdx.x * blockDim.x + threadIdx.x;
    if (i >= O_ * N_) return;
    int b = i / N_;
    int n = i % N_;
    float4 q = g_pip4[i];

    float sd = q.z;                        // plane signed distance
    #pragma unroll 1
    for (int oi = 0; oi < 3; oi++) {
        int pair = b * 3 + oi;
        int o = oi + (oi >= b ? 1 : 0);
        unsigned long long A[KNN], B[KNN], K[KNN];
        #pragma unroll
        for (int s = 0; s < KNN; s++) {
            A[s] = g_part[pair][0][s][n];
            B[s] = g_part[pair][1][s][n];
        }
        // shift-register merge: 10 smallest of A ∪ B (ties: smaller global id wins)
        #pragma unroll
        for (int s = 0; s < KNN; s++) {
            bool ta = A[0] <= B[0];
            K[s] = ta ? A[0] : B[0];
            #pragma unroll
            for (int t = 0; t < KNN - 1; t++) {
                unsigned long long an = A[t + 1], bn = B[t + 1];
                A[t] = ta ? an : A[t];
                B[t] = ta ? B[t] : bn;
            }
            if (ta) A[KNN - 1] = 0xFFFFFFFFFFFFFFFFull;
            else    B[KNN - 1] = 0xFFFFFFFFFFFFFFFFull;
        }
        int votes = 0;
        const float4* pp = g_pip4 + o * N_;
        const float4* nr = g_nrm4 + o * N_;
        #pragma unroll
        for (int s = 0; s < KNN; s++) {
            unsigned id = (unsigned)(K[s] & 0xFFFFFFFFu);
            float4 c  = __ldg(&pp[id]);
            float4 nm = __ldg(&nr[id]);
            float dt = (c.x - q.x) * nm.x + (c.y - q.y) * nm.y + (c.z - q.z) * nm.z;
            votes += (dt > 0.f) ? 1 : 0;
        }
        float dmin = ord2f((unsigned)(K[0] >> 32));
        float D = q.w + dmin;
        float d0 = sqrtf(fmaxf(D, 0.f));
        float s0 = (votes > 8) ? -d0 : d0;
        sd = fminf(sd, s0);
    }
    out[i] = sd;
    if (out_size >= 2 * O_ * N_)
        out[O_ * N_ + i] = (sd < -TOLC) ? 1.0f : 0.0f;
}

// ---------------- launch ----------------
extern "C" void kernel_launch(void* const* d_in, const int* in_sizes, int n_in,
                              void* d_out, int out_size) {
    const float* points  = nullptr;
    const float* T_obj   = nullptr;
    const float* T_plane = nullptr;
    for (int i = 0; i < n_in; i++) {
        if (in_sizes[i] == O_ * N_ * 6) points  = (const float*)d_in[i];
        else if (in_sizes[i] == 64)     T_obj   = (const float*)d_in[i];
        else if (in_sizes[i] == 16)     T_plane = (const float*)d_in[i];
    }

    transform_kernel<<<(O_ * N_ + 255) / 256, 256>>>(points, T_obj, T_plane);

    int smem = LSPL * (int)sizeof(float4) + CAP * BTHR * (int)sizeof(unsigned short);
    (void)cudaFuncSetAttribute(knn_partial_kernel,
                               cudaFuncAttributeMaxDynamicSharedMemorySize, smem);
    knn_partial_kernel<<<dim3(N_ / BTHR, O_ * 3, NSPL), BTHR, smem>>>();

    merge_kernel<<<(O_ * N_ + 127) / 128, 128>>>((float*)d_out, out_size);
}